// round 2
// baseline (speedup 1.0000x reference)
#include <cuda_runtime.h>
#include <math.h>

typedef unsigned long long u64;
typedef unsigned short u16;
typedef unsigned char u8;

#define NN 4096
#define MM 20
#define HH 16
#define NX 32
#define NY 18
#define NLAB 3
#define NCELL (NLAB*NX*NY)   /* 1728 */
#define CAP 64
#define PI_F 3.14159274101257324f
#define QPI_F 0.785398185253143311f
#define COND 0.2f
#define IOUT 0.3f

// ---------------- global scratch (no allocations allowed) ----------------
__device__ float g_b7[NN*7];
__device__ u16   g_pred[NN*CAP];
__device__ u16   g_succ[NN*CAP];
__device__ int   g_nsucc[NN];
__device__ u8    g_status[NN];   // 1=kept 2=suppressed 3=invalid
__device__ int   g_suppby[NN];

// ---------------- dynamic shared layout (bytes) ----------------
#define OFF_KEYS  0         /* u64[4096]  32KB ; reused as int npred[4096] in build/fix */
#define OFF_CNT   32768     /* int[4096]  16KB ; bucket counts -> cellcnt[0..1727] + cellstart[1728..3455] */
#define OFF_START 49152     /* int[4096]  16KB ; bucket starts -> cellid per box */
#define OFF_TEMP  65536     /* int[1024]   4KB ; scan temp */
#define OFF_BX1   69632
#define OFF_BY1   86016
#define OFF_BX2   102400
#define OFF_BY2   118784
#define OFF_AREA  135168
#define OFF_ST    151552    /* u8[4096]  4KB */
#define OFF_CLIST 155648    /* u16[4096] 8KB */
#define SMEM_BYTES 163840

__global__ __launch_bounds__(1024) void k_main(
    const float* __restrict__ pb, const float* __restrict__ ps,
    const int* __restrict__ pl, float* __restrict__ out)
{
    extern __shared__ char sm[];
    u64*   keys    = (u64*)(sm + OFF_KEYS);
    int*   bcnt    = (int*)(sm + OFF_CNT);
    int*   bstart  = (int*)(sm + OFF_START);
    int*   temp    = (int*)(sm + OFF_TEMP);
    float* bx1s    = (float*)(sm + OFF_BX1);
    float* by1s    = (float*)(sm + OFF_BY1);
    float* bx2s    = (float*)(sm + OFF_BX2);
    float* by2s    = (float*)(sm + OFF_BY2);
    float* areas   = (float*)(sm + OFF_AREA);
    u8*    sts     = (u8*)(sm + OFF_ST);
    u16*   clist   = (u16*)(sm + OFF_CLIST);
    __shared__ int done;

    const int t = threadIdx.x;
    const int base = t * 4;

    // ========== phase 1: keys + bucket histogram ==========
    for (int b = t; b < NN; b += 1024) bcnt[b] = 0;
    __syncthreads();

    unsigned keyv[4]; int bk[4]; int invc = 0;
    #pragma unroll
    for (int k = 0; k < 4; k++) {
        int i = base + k;
        float f = ps[i];
        if (f > COND) {
            unsigned u = __float_as_uint(f) | 0x80000000u;  // ascending with f (f>0)
            keyv[k] = ~u;                                   // ascending key == descending f
            int br = (int)(f * 4096.0f);                    // monotone
            int b  = 4096 - br;
            b = min(max(b, 0), 4095);
            bk[k] = b;
            atomicAdd(&bcnt[b], 1);
        } else { bk[k] = -1; invc++; }
    }
    __syncthreads();

    // ========== phase 2: exclusive scan over 4096 buckets ==========
    int myc[4]; int s0 = 0;
    #pragma unroll
    for (int k = 0; k < 4; k++) { myc[k] = bcnt[base + k]; s0 += myc[k]; }
    temp[t] = s0;
    __syncthreads();
    for (int off = 1; off < 1024; off <<= 1) {
        int v = (t >= off) ? temp[t - off] : 0;
        __syncthreads();
        temp[t] += v;
        __syncthreads();
    }
    int vt = temp[1023];                      // total valid
    int run = (t == 0) ? 0 : temp[t - 1];
    #pragma unroll
    for (int k = 0; k < 4; k++) { bstart[base + k] = run; run += myc[k]; }
    __syncthreads();

    // invalid rank prefix (stable by original index)
    temp[t] = invc;
    __syncthreads();
    for (int off = 1; off < 1024; off <<= 1) {
        int v = (t >= off) ? temp[t - off] : 0;
        __syncthreads();
        temp[t] += v;
        __syncthreads();
    }
    int invBase = vt + ((t == 0) ? 0 : temp[t - 1]);

    // ========== phase 3: scatter ==========
    int li = 0;
    #pragma unroll
    for (int k = 0; k < 4; k++) {
        int i = base + k;
        if (bk[k] >= 0) {
            int pos = atomicAdd(&bstart[bk[k]], 1);
            keys[pos] = ((u64)keyv[k] << 32) | (unsigned)i;
        } else {
            keys[invBase + li] = 0xFFFFFFFF00000000ull | (unsigned)i;
            li++;
        }
    }
    __syncthreads();

    // per-bucket insertion sort (bucket segment = [bstart[b]-bcnt[b], bstart[b]))
    for (int b = t; b < NN; b += 1024) {
        int c = bcnt[b];
        if (c > 1) {
            int s = bstart[b] - c;
            for (int a = 1; a < c; a++) {
                u64 v = keys[s + a];
                int q = a - 1;
                while (q >= 0 && keys[s + q] > v) { keys[s + q + 1] = keys[s + q]; q--; }
                keys[s + q + 1] = v;
            }
        }
    }
    __syncthreads();

    // ========== phase 4: gather, BEV, cell histogram, baseline outputs ==========
    int* ccnt   = bcnt;            // [0..1727]
    int* cstart = bcnt + 1728;     // [0..1727]
    int* cellid = bstart;          // per-box cell
    for (int c = t; c < NCELL; c += 1024) ccnt[c] = 0;
    __syncthreads();

    #pragma unroll
    for (int k = 0; k < 4; k++) {
        int i = base + k;
        int idx = (int)(keys[i] & 0xFFFFFFFFu);
        float b[9];
        #pragma unroll
        for (int c = 0; c < 9; c++) b[c] = pb[idx*9 + c];
        #pragma unroll
        for (int c = 0; c < 7; c++) { g_b7[i*7 + c] = b[c]; out[i*9 + c] = b[c]; }
        out[i*9 + 7] = b[7];
        out[i*9 + 8] = b[8];
        float sc = ps[idx];
        out[NN*9  + i] = sc;
        int lab = pl[idx];
        out[NN*10 + i] = (float)lab;
        sts[i] = (sc > COND) ? 0 : 3;

        float h   = b[6];
        float ang = h - floorf(h / PI_F + 0.5f) * PI_F;
        bool  sw  = fabsf(ang) >= QPI_F;
        float dx  = sw ? b[4] : b[3];
        float dy  = sw ? b[3] : b[4];
        bx1s[i] = b[0] - dx * 0.5f;
        by1s[i] = b[1] - dy * 0.5f;
        bx2s[i] = b[0] + dx * 0.5f;
        by2s[i] = b[1] + dy * 0.5f;
        areas[i] = dx * dy;

        int cx = (int)floorf((b[0] + 70.0f) * (1.0f / 4.5f)); cx = min(max(cx, 0), NX-1);
        int cy = (int)floorf((b[1] + 40.0f) * (1.0f / 4.5f)); cy = min(max(cy, 0), NY-1);
        int cell = (lab * NY + cy) * NX + cx;
        cellid[i] = cell;
        atomicAdd(&ccnt[cell], 1);
    }
    __syncthreads();

    // ========== phase 5: cell scan + fill ==========
    {
        int c0 = 2*t, c1 = 2*t + 1;
        int a  = (c0 < NCELL) ? ccnt[c0] : 0;
        int b2 = (c1 < NCELL) ? ccnt[c1] : 0;
        temp[t] = a + b2;
        __syncthreads();
        for (int off = 1; off < 1024; off <<= 1) {
            int v = (t >= off) ? temp[t - off] : 0;
            __syncthreads();
            temp[t] += v;
            __syncthreads();
        }
        int excl = (t == 0) ? 0 : temp[t - 1];
        if (c0 < NCELL) cstart[c0] = excl;
        if (c1 < NCELL) cstart[c1] = excl + a;
    }
    __syncthreads();
    #pragma unroll
    for (int k = 0; k < 4; k++) {
        int i = base + k;
        int pos = atomicAdd(&cstart[cellid[i]], 1);
        clist[pos] = (u16)i;
    }
    __syncthreads();
    // now: cell segment = [cstart[c]-ccnt[c], cstart[c])

    // ========== phase 6: build overlap pred/succ lists ==========
    int* npred_s = (int*)keys;   // keys no longer needed
    #pragma unroll
    for (int k = 0; k < 4; k++) {
        int i = base + k;
        float ax1 = bx1s[i], ay1 = by1s[i], ax2 = bx2s[i], ay2 = by2s[i], aa = areas[i];
        int cell = cellid[i];
        int cx = cell % NX, cy = (cell / NX) % NY, lab = cell / (NX * NY);
        int np = 0, ns = 0;
        for (int dy = -1; dy <= 1; dy++) {
            int yy = cy + dy; if (yy < 0 || yy >= NY) continue;
            for (int dx = -1; dx <= 1; dx++) {
                int xx = cx + dx; if (xx < 0 || xx >= NX) continue;
                int c2 = (lab * NY + yy) * NX + xx;
                int e1 = cstart[c2], s1 = e1 - ccnt[c2];
                for (int p = s1; p < e1; p++) {
                    int j = clist[p];
                    if (j == i) continue;
                    float ix = fminf(ax2, bx2s[j]) - fmaxf(ax1, bx1s[j]);
                    float iy = fminf(ay2, by2s[j]) - fmaxf(ay1, by1s[j]);
                    float inter = fmaxf(ix, 0.0f) * fmaxf(iy, 0.0f);
                    float uni   = aa + areas[j] - inter;
                    if (inter > IOUT * fmaxf(uni, 1e-6f)) {
                        if (j < i) { if (np < CAP) g_pred[i*CAP + np++] = (u16)j; }
                        else       { if (ns < CAP) g_succ[i*CAP + ns++] = (u16)j; }
                    }
                }
            }
        }
        // succ ascending (cluster member order)
        for (int a = 1; a < ns; a++) {
            u16 v = g_succ[i*CAP + a];
            int b = a - 1;
            while (b >= 0 && g_succ[i*CAP + b] > v) { g_succ[i*CAP + b + 1] = g_succ[i*CAP + b]; b--; }
            g_succ[i*CAP + b + 1] = v;
        }
        npred_s[i] = np;
        g_nsucc[i] = ns;
    }
    __syncthreads();

    // ========== phase 7: keep-set fixpoint (monotone chaotic relaxation) ==========
    {
        volatile u8* st = sts;
        for (int round = 0; round < NN; round++) {
            if (t == 0) done = 1;
            __syncthreads();
            for (int i = t; i < NN; i += 1024) {
                if (st[i] == 0) {
                    int np = npred_s[i];
                    bool anyK = false, allS = true;
                    for (int p = 0; p < np; p++) {
                        u8 s = st[g_pred[i*CAP + p]];
                        anyK |= (s == 1);
                        allS &= (s >= 2);
                    }
                    if (anyK)      st[i] = 2;
                    else if (allS) st[i] = 1;
                    else           done = 0;
                }
            }
            __syncthreads();
            if (done) break;
        }
    }

    // ========== phase 8: suppby + keep flags ==========
    for (int i = t; i < NN; i += 1024) {
        u8 s = sts[i];
        g_status[i] = s;
        out[NN*11 + i] = (s == 1) ? 1.0f : 0.0f;
        int sb;
        if (s == 1) sb = i;
        else if (s == 3) sb = -1;
        else {
            int np = npred_s[i];
            int best = 0x7FFFFFFF;
            for (int p = 0; p < np; p++) {
                int q = g_pred[i*CAP + p];
                if (sts[q] == 1 && q < best) best = q;
            }
            sb = best;
        }
        g_suppby[i] = sb;
    }
}

// ---------------- merge MLP for kept clusters with count>1 ----------------
__global__ void k_merge(const float* __restrict__ w1, const float* __restrict__ b1,
                        const float* __restrict__ w2, const float* __restrict__ b2,
                        const float* __restrict__ w3, const float* __restrict__ b3,
                        float* __restrict__ out) {
    __shared__ float s_w1[MM*HH], s_w2[HH*HH], s_w3[HH], s_b1[HH], s_b2[HH], s_b3;
    int t = threadIdx.x;
    for (int k = t; k < MM*HH; k += blockDim.x) s_w1[k] = w1[k];
    for (int k = t; k < HH*HH; k += blockDim.x) s_w2[k] = w2[k];
    if (t < HH) { s_w3[t] = w3[t]; s_b1[t] = b1[t]; s_b2[t] = b2[t]; }
    if (t == 0) s_b3 = b3[0];
    __syncthreads();

    int i = blockIdx.x * blockDim.x + t;
    if (i >= NN) return;
    if (g_status[i] != 1) return;

    int ns = g_nsucc[i];
    int mem[MM];
    mem[0] = i;
    int cnt = 1, total = 1;
    for (int a = 0; a < ns; a++) {
        int j = g_succ[i*CAP + a];
        if (g_suppby[j] == i) { total++; if (cnt < MM) mem[cnt++] = j; }
    }
    if (total <= 1) return;   // baseline row already written by k_main

    float ob[7];
    for (int c = 0; c < 7; c++) {
        float h1[HH];
        #pragma unroll
        for (int h = 0; h < HH; h++) h1[h] = s_b1[h];
        for (int m = 0; m < cnt; m++) {
            float xv = g_b7[mem[m]*7 + c];
            #pragma unroll
            for (int h = 0; h < HH; h++) h1[h] += xv * s_w1[m*HH + h];
        }
        #pragma unroll
        for (int h = 0; h < HH; h++) h1[h] = fmaxf(h1[h], 0.0f);
        float h2[HH];
        #pragma unroll
        for (int q = 0; q < HH; q++) h2[q] = s_b2[q];
        #pragma unroll
        for (int h = 0; h < HH; h++) {
            float v = h1[h];
            #pragma unroll
            for (int q = 0; q < HH; q++) h2[q] += v * s_w2[h*HH + q];
        }
        float acc = s_b3;
        #pragma unroll
        for (int q = 0; q < HH; q++) acc += fmaxf(h2[q], 0.0f) * s_w3[q];
        ob[c] = acc;
    }
    ob[3] = fmaxf(ob[3], 1e-5f);
    ob[4] = fmaxf(ob[4], 1e-5f);
    ob[5] = fmaxf(ob[5], 1e-5f);
    #pragma unroll
    for (int c = 0; c < 7; c++) out[i*9 + c] = ob[c];
}

extern "C" void kernel_launch(void* const* d_in, const int* in_sizes, int n_in,
                              void* d_out, int out_size) {
    const float* pb = (const float*)d_in[0];
    const float* ps = (const float*)d_in[1];
    const int*   pl = (const int*)  d_in[2];
    const float* w1 = (const float*)d_in[3];
    const float* b1 = (const float*)d_in[4];
    const float* w2 = (const float*)d_in[5];
    const float* b2 = (const float*)d_in[6];
    const float* w3 = (const float*)d_in[7];
    const float* b3 = (const float*)d_in[8];
    float* out = (float*)d_out;

    cudaFuncSetAttribute(k_main, cudaFuncAttributeMaxDynamicSharedMemorySize, SMEM_BYTES);
    k_main<<<1, 1024, SMEM_BYTES>>>(pb, ps, pl, out);
    k_merge<<<16, 256>>>(w1, b1, w2, b2, w3, b3, out);
}

// round 3
// speedup vs baseline: 1.1445x; 1.1445x over previous
#include <cuda_runtime.h>
#include <math.h>

typedef unsigned long long u64;
typedef unsigned short u16;
typedef unsigned char u8;

#define NN 4096
#define MM 20
#define HH 16
#define NX 32
#define NY 18
#define NLAB 3
#define NCELL (NLAB*NX*NY)   /* 1728 */
#define CAP 64
#define PI_F 3.14159274101257324f
#define QPI_F 0.785398185253143311f
#define COND 0.2f
#define IOUT 0.3f

// ---------------- global scratch (no allocations allowed) ----------------
__device__ float  g_b7[NN*7];
__device__ float4 g_bev[NN];          // x1,y1,x2,y2
__device__ float  g_area[NN];
__device__ int    g_cellid[NN];
__device__ int    g_cellbeg[NCELL];
__device__ int    g_cellcnt_g[NCELL];
__device__ u16    g_clist[NN];
__device__ u8     g_sts0[NN];         // 0=unknown 3=invalid
__device__ u16    g_pred[NN*CAP];
__device__ u16    g_succ[NN*CAP];
__device__ int    g_npred[NN], g_nsucc[NN];
__device__ int    g_nwork;
__device__ int    g_work[2048];       // kept cluster head i
__device__ int    g_wcnt[2048];       // member count (capped at MM)
__device__ u16    g_wmem[2048*MM];    // member indices

// ============ 1) single-block: sort + gather + bev + cell lists ============
// dynamic smem layout
#define OFF_KEYS  0         /* u64[4096] 32KB */
#define OFF_CNT   32768     /* int[4096] 16KB : buckets; later ccnt[0..1727]+cursor[1728..3455] */
#define OFF_START 49152     /* int[4096] 16KB : bucket starts; later cellid per box */
#define OFF_TEMP  65536     /* int[1024]  4KB */
#define SMEM_A    69632

__global__ __launch_bounds__(1024) void k_pre(
    const float* __restrict__ pb, const float* __restrict__ ps,
    const int* __restrict__ pl, float* __restrict__ out)
{
    extern __shared__ char sm[];
    u64* keys   = (u64*)(sm + OFF_KEYS);
    int* bcnt   = (int*)(sm + OFF_CNT);
    int* bstart = (int*)(sm + OFF_START);
    int* temp   = (int*)(sm + OFF_TEMP);

    const int t = threadIdx.x;
    const int base = t * 4;
    if (t == 0) g_nwork = 0;

    // ---- bucket histogram ----
    for (int b = t; b < NN; b += 1024) bcnt[b] = 0;
    __syncthreads();

    unsigned keyv[4]; int bk[4]; int invc = 0;
    #pragma unroll
    for (int k = 0; k < 4; k++) {
        int i = base + k;
        float f = ps[i];
        if (f > COND) {
            unsigned u = __float_as_uint(f) | 0x80000000u;
            keyv[k] = ~u;                           // ascending key == descending f
            int b = 4096 - (int)(f * 4096.0f);
            b = min(max(b, 0), 4095);
            bk[k] = b;
            atomicAdd(&bcnt[b], 1);
        } else { bk[k] = -1; invc++; }
    }
    __syncthreads();

    // ---- exclusive scan over 4096 buckets ----
    int myc[4]; int s0 = 0;
    #pragma unroll
    for (int k = 0; k < 4; k++) { myc[k] = bcnt[base + k]; s0 += myc[k]; }
    temp[t] = s0;
    __syncthreads();
    for (int off = 1; off < 1024; off <<= 1) {
        int v = (t >= off) ? temp[t - off] : 0;
        __syncthreads();
        temp[t] += v;
        __syncthreads();
    }
    int vt = temp[1023];
    int run = (t == 0) ? 0 : temp[t - 1];
    #pragma unroll
    for (int k = 0; k < 4; k++) { bstart[base + k] = run; run += myc[k]; }
    __syncthreads();

    // invalid rank prefix (stable by index)
    temp[t] = invc;
    __syncthreads();
    for (int off = 1; off < 1024; off <<= 1) {
        int v = (t >= off) ? temp[t - off] : 0;
        __syncthreads();
        temp[t] += v;
        __syncthreads();
    }
    int invBase = vt + ((t == 0) ? 0 : temp[t - 1]);

    // ---- scatter ----
    int li = 0;
    #pragma unroll
    for (int k = 0; k < 4; k++) {
        int i = base + k;
        if (bk[k] >= 0) {
            int pos = atomicAdd(&bstart[bk[k]], 1);
            keys[pos] = ((u64)keyv[k] << 32) | (unsigned)i;
        } else {
            keys[invBase + li] = 0xFFFFFFFF00000000ull | (unsigned)i;
            li++;
        }
    }
    __syncthreads();

    // per-bucket insertion sort; segment = [bstart[b]-bcnt[b], bstart[b])
    for (int b = t; b < NN; b += 1024) {
        int c = bcnt[b];
        if (c > 1) {
            int s = bstart[b] - c;
            for (int a = 1; a < c; a++) {
                u64 v = keys[s + a];
                int q = a - 1;
                while (q >= 0 && keys[s + q] > v) { keys[s + q + 1] = keys[s + q]; q--; }
                keys[s + q + 1] = v;
            }
        }
    }
    __syncthreads();

    // ---- gather, BEV, cell histogram ----
    int* ccnt   = bcnt;          // [0..1727]
    int* cursor = bcnt + 1728;   // [0..1727]
    int* cellid = bstart;        // per-box
    for (int c = t; c < NCELL; c += 1024) ccnt[c] = 0;
    __syncthreads();

    #pragma unroll
    for (int k = 0; k < 4; k++) {
        int i = base + k;
        int idx = (int)(keys[i] & 0xFFFFFFFFu);
        float b[9];
        #pragma unroll
        for (int c = 0; c < 9; c++) b[c] = pb[idx*9 + c];
        #pragma unroll
        for (int c = 0; c < 7; c++) { g_b7[i*7 + c] = b[c]; out[i*9 + c] = b[c]; }
        out[i*9 + 7] = b[7];
        out[i*9 + 8] = b[8];
        float sc = ps[idx];
        out[NN*9  + i] = sc;
        int lab = pl[idx];
        out[NN*10 + i] = (float)lab;
        g_sts0[i] = (sc > COND) ? 0 : 3;

        float h   = b[6];
        float ang = h - floorf(h / PI_F + 0.5f) * PI_F;
        bool  sw  = fabsf(ang) >= QPI_F;
        float dx  = sw ? b[4] : b[3];
        float dy  = sw ? b[3] : b[4];
        float4 bv;
        bv.x = b[0] - dx * 0.5f;
        bv.y = b[1] - dy * 0.5f;
        bv.z = b[0] + dx * 0.5f;
        bv.w = b[1] + dy * 0.5f;
        g_bev[i]  = bv;
        g_area[i] = dx * dy;

        int cx = (int)floorf((b[0] + 70.0f) * (1.0f / 4.5f)); cx = min(max(cx, 0), NX-1);
        int cy = (int)floorf((b[1] + 40.0f) * (1.0f / 4.5f)); cy = min(max(cy, 0), NY-1);
        int cell = (lab * NY + cy) * NX + cx;
        cellid[i] = cell;
        atomicAdd(&ccnt[cell], 1);
    }
    __syncthreads();

    // ---- cell exclusive scan + fill ----
    {
        int c0 = 2*t, c1 = 2*t + 1;
        int a  = (c0 < NCELL) ? ccnt[c0] : 0;
        int b2 = (c1 < NCELL) ? ccnt[c1] : 0;
        temp[t] = a + b2;
        __syncthreads();
        for (int off = 1; off < 1024; off <<= 1) {
            int v = (t >= off) ? temp[t - off] : 0;
            __syncthreads();
            temp[t] += v;
            __syncthreads();
        }
        int excl = (t == 0) ? 0 : temp[t - 1];
        if (c0 < NCELL) { cursor[c0] = excl;     g_cellbeg[c0] = excl;     g_cellcnt_g[c0] = a;  }
        if (c1 < NCELL) { cursor[c1] = excl + a; g_cellbeg[c1] = excl + a; g_cellcnt_g[c1] = b2; }
    }
    __syncthreads();
    #pragma unroll
    for (int k = 0; k < 4; k++) {
        int i = base + k;
        int cell = cellid[i];
        g_cellid[i] = cell;
        int pos = atomicAdd(&cursor[cell], 1);
        g_clist[pos] = (u16)i;
    }
}

// ============ 2) multi-block: build overlap pred/succ lists ============
__global__ __launch_bounds__(256) void k_build() {
    int i = blockIdx.x * 256 + threadIdx.x;
    if (i >= NN) return;
    float4 a = g_bev[i];
    float aa = g_area[i];
    int cell = g_cellid[i];
    int cx = cell % NX, cy = (cell / NX) % NY, lab = cell / (NX * NY);
    int np = 0, ns = 0;
    for (int dy = -1; dy <= 1; dy++) {
        int yy = cy + dy; if (yy < 0 || yy >= NY) continue;
        for (int dx = -1; dx <= 1; dx++) {
            int xx = cx + dx; if (xx < 0 || xx >= NX) continue;
            int c2 = (lab * NY + yy) * NX + xx;
            int s0 = g_cellbeg[c2], s1 = s0 + g_cellcnt_g[c2];
            for (int p = s0; p < s1; p++) {
                int j = g_clist[p];
                if (j == i) continue;
                float4 bb = g_bev[j];
                float ix = fminf(a.z, bb.z) - fmaxf(a.x, bb.x);
                float iy = fminf(a.w, bb.w) - fmaxf(a.y, bb.y);
                float inter = fmaxf(ix, 0.0f) * fmaxf(iy, 0.0f);
                float uni   = aa + g_area[j] - inter;
                if (inter > IOUT * fmaxf(uni, 1e-6f)) {
                    if (j < i) { if (np < CAP) g_pred[i*CAP + np++] = (u16)j; }
                    else       { if (ns < CAP) g_succ[i*CAP + ns++] = (u16)j; }
                }
            }
        }
    }
    // succ ascending (cluster member order)
    for (int a2 = 1; a2 < ns; a2++) {
        u16 v = g_succ[i*CAP + a2];
        int b = a2 - 1;
        while (b >= 0 && g_succ[i*CAP + b] > v) { g_succ[i*CAP + b + 1] = g_succ[i*CAP + b]; b--; }
        g_succ[i*CAP + b + 1] = v;
    }
    g_npred[i] = np;
    g_nsucc[i] = ns;
}

// ============ 3) single-block: fixpoint + suppby + worklist ============
__global__ __launch_bounds__(1024) void k_fix(float* __restrict__ out) {
    __shared__ u8  sts_[NN];
    __shared__ int sby[NN];
    __shared__ int done;
    volatile u8* st = sts_;
    const int t = threadIdx.x;
    for (int i = t; i < NN; i += 1024) sts_[i] = g_sts0[i];
    __syncthreads();

    // chaotic relaxation: kept iff all overlapping preds suppressed/invalid
    for (int round = 0; round < NN; round++) {
        if (t == 0) done = 1;
        __syncthreads();
        for (int i = t; i < NN; i += 1024) {
            if (st[i] == 0) {
                int np = g_npred[i];
                bool anyK = false, allS = true;
                for (int p = 0; p < np; p++) {
                    u8 s = st[g_pred[i*CAP + p]];
                    anyK |= (s == 1);
                    allS &= (s >= 2);
                }
                if (anyK)      st[i] = 2;
                else if (allS) st[i] = 1;
                else           done = 0;
            }
        }
        __syncthreads();
        if (done) break;
    }

    // suppby = min kept overlapping predecessor (self if kept, -1 if invalid)
    for (int i = t; i < NN; i += 1024) {
        u8 s = sts_[i];
        out[NN*11 + i] = (s == 1) ? 1.0f : 0.0f;
        int sb;
        if (s == 1) sb = i;
        else if (s == 3) sb = -1;
        else {
            int np = g_npred[i];
            int best = 0x7FFFFFFF;
            for (int p = 0; p < np; p++) {
                int q = g_pred[i*CAP + p];
                if (sts_[q] == 1 && q < best) best = q;
            }
            sb = best;
        }
        sby[i] = sb;
    }
    __syncthreads();

    // worklist: kept clusters with >1 member
    for (int i = t; i < NN; i += 1024) {
        if (sts_[i] != 1) continue;
        int ns = g_nsucc[i];
        u16 mem[MM];
        mem[0] = (u16)i;
        int cnt = 1, total = 1;
        for (int a = 0; a < ns; a++) {
            int j = g_succ[i*CAP + a];
            if (sby[j] == i) { total++; if (cnt < MM) mem[cnt++] = (u16)j; }
        }
        if (total > 1) {
            int w = atomicAdd(&g_nwork, 1);
            g_work[w] = i;
            g_wcnt[w] = cnt;
            #pragma unroll
            for (int m = 0; m < MM; m++) if (m < cnt) g_wmem[w*MM + m] = mem[m];
        }
    }
}

// ============ 4) merge MLP: one thread per (cluster, channel) ============
__global__ __launch_bounds__(256) void k_merge(
    const float* __restrict__ w1, const float* __restrict__ b1,
    const float* __restrict__ w2, const float* __restrict__ b2,
    const float* __restrict__ w3, const float* __restrict__ b3,
    float* __restrict__ out)
{
    __shared__ float s_w1[MM*HH], s_w2[HH*HH], s_w3[HH], s_b1[HH], s_b2[HH], s_b3;
    const int t = threadIdx.x;
    for (int k = t; k < MM*HH; k += 256) s_w1[k] = w1[k];
    for (int k = t; k < HH*HH; k += 256) s_w2[k] = w2[k];
    if (t < HH) { s_w3[t] = w3[t]; s_b1[t] = b1[t]; s_b2[t] = b2[t]; }
    if (t == 0) s_b3 = b3[0];
    __syncthreads();

    int gt = blockIdx.x * 256 + t;
    int w  = gt >> 3;          // cluster index
    int c  = gt & 7;           // channel (0..6 active)
    if (c >= 7 || w >= g_nwork) return;

    int i   = g_work[w];
    int cnt = g_wcnt[w];

    float h1[HH];
    #pragma unroll
    for (int h = 0; h < HH; h++) h1[h] = s_b1[h];
    for (int m = 0; m < cnt; m++) {
        int j = g_wmem[w*MM + m];
        float xv = g_b7[j*7 + c];
        #pragma unroll
        for (int h = 0; h < HH; h++) h1[h] += xv * s_w1[m*HH + h];
    }
    #pragma unroll
    for (int h = 0; h < HH; h++) h1[h] = fmaxf(h1[h], 0.0f);
    float h2[HH];
    #pragma unroll
    for (int q = 0; q < HH; q++) h2[q] = s_b2[q];
    #pragma unroll
    for (int h = 0; h < HH; h++) {
        float v = h1[h];
        #pragma unroll
        for (int q = 0; q < HH; q++) h2[q] += v * s_w2[h*HH + q];
    }
    float acc = s_b3;
    #pragma unroll
    for (int q = 0; q < HH; q++) acc += fmaxf(h2[q], 0.0f) * s_w3[q];

    if (c >= 3 && c <= 5) acc = fmaxf(acc, 1e-5f);
    out[i*9 + c] = acc;
}

extern "C" void kernel_launch(void* const* d_in, const int* in_sizes, int n_in,
                              void* d_out, int out_size) {
    const float* pb = (const float*)d_in[0];
    const float* ps = (const float*)d_in[1];
    const int*   pl = (const int*)  d_in[2];
    const float* w1 = (const float*)d_in[3];
    const float* b1 = (const float*)d_in[4];
    const float* w2 = (const float*)d_in[5];
    const float* b2 = (const float*)d_in[6];
    const float* w3 = (const float*)d_in[7];
    const float* b3 = (const float*)d_in[8];
    float* out = (float*)d_out;

    cudaFuncSetAttribute(k_pre, cudaFuncAttributeMaxDynamicSharedMemorySize, SMEM_A);
    k_pre<<<1, 1024, SMEM_A>>>(pb, ps, pl, out);
    k_build<<<16, 256>>>();
    k_fix<<<1, 1024>>>(out);
    k_merge<<<64, 256>>>(w1, b1, w2, b2, w3, b3, out);
}

// round 4
// speedup vs baseline: 2.0920x; 1.8279x over previous
#include <cuda_runtime.h>
#include <math.h>

typedef unsigned long long u64;
typedef unsigned short u16;
typedef unsigned char u8;

#define NN 4096
#define MM 20
#define HH 16
#define NX 32
#define NY 18
#define NLAB 3
#define NCELL (NLAB*NX*NY)   /* 1728 */
#define CAP 64
#define CAPC 28
#define PI_F 3.14159274101257324f
#define QPI_F 0.785398185253143311f
#define COND 0.2f
#define IOUT 0.3f

// ---------------- global scratch (no allocations allowed) ----------------
__device__ int    g_rank[NN];         // original idx -> sorted pos
__device__ int    g_vt;               // number of valid boxes
__device__ float  g_b7[NN*7];
__device__ float4 g_bev[NN];
__device__ float  g_area[NN];
__device__ int    g_cellid[NN];
__device__ int    g_cellcnt[NCELL];
__device__ u16    g_cellbox[NCELL*CAPC];
__device__ u16    g_pred[NN*CAP];
__device__ u16    g_succ[NN*CAP];
__device__ int    g_npred[NN], g_nsucc[NN];
__device__ int    g_nwork;
__device__ int    g_work[2048];
__device__ int    g_wcnt[2048];
__device__ u16    g_wmem[2048*MM];

// ============ 1) single-block sort: only reads scores, writes rank ============
#define OFF_KEYS  0         /* u64[4096] 32KB */
#define OFF_CNT   32768     /* int[4096] 16KB */
#define OFF_START 49152     /* int[4096] 16KB */
#define OFF_TEMP  65536     /* int[1024]  4KB */
#define SMEM_A    69632

__global__ __launch_bounds__(1024) void k_sort(const float* __restrict__ ps)
{
    extern __shared__ char sm[];
    u64* keys   = (u64*)(sm + OFF_KEYS);
    int* bcnt   = (int*)(sm + OFF_CNT);
    int* bstart = (int*)(sm + OFF_START);
    int* temp   = (int*)(sm + OFF_TEMP);

    const int t = threadIdx.x;
    const int base = t * 4;
    if (t == 0) g_nwork = 0;
    for (int c = t; c < NCELL; c += 1024) g_cellcnt[c] = 0;

    for (int b = t; b < NN; b += 1024) bcnt[b] = 0;
    __syncthreads();

    unsigned keyv[4]; int bk[4]; int invc = 0;
    #pragma unroll
    for (int k = 0; k < 4; k++) {
        int i = base + k;
        float f = ps[i];
        if (f > COND) {
            unsigned u = __float_as_uint(f) | 0x80000000u;
            keyv[k] = ~u;                            // ascending key == descending f
            int b = 4096 - (int)(f * 4096.0f);
            b = min(max(b, 0), 4095);
            bk[k] = b;
            atomicAdd(&bcnt[b], 1);
        } else { bk[k] = -1; invc++; }
    }
    __syncthreads();

    // exclusive scan over 4096 buckets
    int myc[4]; int s0 = 0;
    #pragma unroll
    for (int k = 0; k < 4; k++) { myc[k] = bcnt[base + k]; s0 += myc[k]; }
    temp[t] = s0;
    __syncthreads();
    for (int off = 1; off < 1024; off <<= 1) {
        int v = (t >= off) ? temp[t - off] : 0;
        __syncthreads();
        temp[t] += v;
        __syncthreads();
    }
    int vt = temp[1023];
    if (t == 0) g_vt = vt;
    int run = (t == 0) ? 0 : temp[t - 1];
    #pragma unroll
    for (int k = 0; k < 4; k++) { bstart[base + k] = run; run += myc[k]; }
    __syncthreads();

    // invalid rank prefix (stable by original index)
    temp[t] = invc;
    __syncthreads();
    for (int off = 1; off < 1024; off <<= 1) {
        int v = (t >= off) ? temp[t - off] : 0;
        __syncthreads();
        temp[t] += v;
        __syncthreads();
    }
    int invBase = vt + ((t == 0) ? 0 : temp[t - 1]);

    // scatter
    int li = 0;
    #pragma unroll
    for (int k = 0; k < 4; k++) {
        int i = base + k;
        if (bk[k] >= 0) {
            int pos = atomicAdd(&bstart[bk[k]], 1);
            keys[pos] = ((u64)keyv[k] << 32) | (unsigned)i;
        } else {
            keys[invBase + li] = 0xFFFFFFFF00000000ull | (unsigned)i;
            li++;
        }
    }
    __syncthreads();

    // per-bucket insertion sort (segment = [bstart[b]-bcnt[b], bstart[b]))
    for (int b = t; b < NN; b += 1024) {
        int c = bcnt[b];
        if (c > 1) {
            int s = bstart[b] - c;
            for (int a = 1; a < c; a++) {
                u64 v = keys[s + a];
                int q = a - 1;
                while (q >= 0 && keys[s + q] > v) { keys[s + q + 1] = keys[s + q]; q--; }
                keys[s + q + 1] = v;
            }
        }
    }
    __syncthreads();

    // write inverse permutation
    #pragma unroll
    for (int k = 0; k < 4; k++) {
        int i = base + k;
        int idx = (int)(keys[i] & 0xFFFFFFFFu);
        g_rank[idx] = i;
    }
}

// ============ 2) multi-block gather: coalesced reads by original idx ============
__global__ __launch_bounds__(256) void k_gather(
    const float* __restrict__ pb, const float* __restrict__ ps,
    const int* __restrict__ pl, float* __restrict__ out)
{
    int idx = blockIdx.x * 256 + threadIdx.x;
    if (idx >= NN) return;
    int i = g_rank[idx];

    float b[9];
    #pragma unroll
    for (int c = 0; c < 9; c++) b[c] = pb[idx*9 + c];
    #pragma unroll
    for (int c = 0; c < 7; c++) { g_b7[i*7 + c] = b[c]; out[i*9 + c] = b[c]; }
    out[i*9 + 7] = b[7];
    out[i*9 + 8] = b[8];
    out[NN*9  + i] = ps[idx];
    int lab = pl[idx];
    out[NN*10 + i] = (float)lab;

    float h   = b[6];
    float ang = h - floorf(h / PI_F + 0.5f) * PI_F;
    bool  sw  = fabsf(ang) >= QPI_F;
    float dx  = sw ? b[4] : b[3];
    float dy  = sw ? b[3] : b[4];
    float4 bv;
    bv.x = b[0] - dx * 0.5f;
    bv.y = b[1] - dy * 0.5f;
    bv.z = b[0] + dx * 0.5f;
    bv.w = b[1] + dy * 0.5f;
    g_bev[i]  = bv;
    g_area[i] = dx * dy;

    int cx = (int)floorf((b[0] + 70.0f) * (1.0f / 4.5f)); cx = min(max(cx, 0), NX-1);
    int cy = (int)floorf((b[1] + 40.0f) * (1.0f / 4.5f)); cy = min(max(cy, 0), NY-1);
    int cell = (lab * NY + cy) * NX + cx;
    g_cellid[i] = cell;
    int pos = atomicAdd(&g_cellcnt[cell], 1);
    if (pos < CAPC) g_cellbox[cell*CAPC + pos] = (u16)i;
}

// ============ 3) multi-block: build overlap pred/succ lists ============
__global__ __launch_bounds__(256) void k_build() {
    int i = blockIdx.x * 256 + threadIdx.x;
    if (i >= NN) return;
    float4 a = g_bev[i];
    float aa = g_area[i];
    int cell = g_cellid[i];
    int cx = cell % NX, cy = (cell / NX) % NY, lab = cell / (NX * NY);
    int np = 0, ns = 0;
    for (int dy = -1; dy <= 1; dy++) {
        int yy = cy + dy; if (yy < 0 || yy >= NY) continue;
        for (int dx = -1; dx <= 1; dx++) {
            int xx = cx + dx; if (xx < 0 || xx >= NX) continue;
            int c2 = (lab * NY + yy) * NX + xx;
            int cnt2 = min(g_cellcnt[c2], CAPC);
            for (int p = 0; p < cnt2; p++) {
                int j = g_cellbox[c2*CAPC + p];
                if (j == i) continue;
                float4 bb = g_bev[j];
                float ix = fminf(a.z, bb.z) - fmaxf(a.x, bb.x);
                float iy = fminf(a.w, bb.w) - fmaxf(a.y, bb.y);
                float inter = fmaxf(ix, 0.0f) * fmaxf(iy, 0.0f);
                float uni   = aa + g_area[j] - inter;
                if (inter > IOUT * fmaxf(uni, 1e-6f)) {
                    if (j < i) { if (np < CAP) g_pred[i*CAP + np++] = (u16)j; }
                    else       { if (ns < CAP) g_succ[i*CAP + ns++] = (u16)j; }
                }
            }
        }
    }
    // succ ascending (cluster member order)
    for (int a2 = 1; a2 < ns; a2++) {
        u16 v = g_succ[i*CAP + a2];
        int b = a2 - 1;
        while (b >= 0 && g_succ[i*CAP + b] > v) { g_succ[i*CAP + b + 1] = g_succ[i*CAP + b]; b--; }
        g_succ[i*CAP + b + 1] = v;
    }
    g_npred[i] = np;
    g_nsucc[i] = ns;
}

// ============ 4) single-block: fixpoint + suppby + worklist ============
__global__ __launch_bounds__(1024) void k_fix(float* __restrict__ out) {
    __shared__ u8  sts_[NN];
    __shared__ int sby[NN];
    __shared__ int done;
    volatile u8* st = sts_;
    const int t = threadIdx.x;
    const int vt = g_vt;
    for (int i = t; i < NN; i += 1024) sts_[i] = (i < vt) ? 0 : 3;
    __syncthreads();

    for (int round = 0; round < NN; round++) {
        if (t == 0) done = 1;
        __syncthreads();
        for (int i = t; i < vt; i += 1024) {
            if (st[i] == 0) {
                int np = g_npred[i];
                bool anyK = false, allS = true;
                for (int p = 0; p < np; p++) {
                    u8 s = st[g_pred[i*CAP + p]];
                    anyK |= (s == 1);
                    allS &= (s >= 2);
                }
                if (anyK)      st[i] = 2;
                else if (allS) st[i] = 1;
                else           done = 0;
            }
        }
        __syncthreads();
        if (done) break;
    }

    for (int i = t; i < NN; i += 1024) {
        u8 s = sts_[i];
        out[NN*11 + i] = (s == 1) ? 1.0f : 0.0f;
        int sb;
        if (s == 1) sb = i;
        else if (s == 3) sb = -1;
        else {
            int np = g_npred[i];
            int best = 0x7FFFFFFF;
            for (int p = 0; p < np; p++) {
                int q = g_pred[i*CAP + p];
                if (sts_[q] == 1 && q < best) best = q;
            }
            sb = best;
        }
        sby[i] = sb;
    }
    __syncthreads();

    for (int i = t; i < NN; i += 1024) {
        if (sts_[i] != 1) continue;
        int ns = g_nsucc[i];
        u16 mem[MM];
        mem[0] = (u16)i;
        int cnt = 1, total = 1;
        for (int a = 0; a < ns; a++) {
            int j = g_succ[i*CAP + a];
            if (sby[j] == i) { total++; if (cnt < MM) mem[cnt++] = (u16)j; }
        }
        if (total > 1) {
            int w = atomicAdd(&g_nwork, 1);
            g_work[w] = i;
            g_wcnt[w] = cnt;
            #pragma unroll
            for (int m = 0; m < MM; m++) if (m < cnt) g_wmem[w*MM + m] = mem[m];
        }
    }
}

// ============ 5) merge MLP: one thread per (cluster, channel) ============
__global__ __launch_bounds__(256) void k_merge(
    const float* __restrict__ w1, const float* __restrict__ b1,
    const float* __restrict__ w2, const float* __restrict__ b2,
    const float* __restrict__ w3, const float* __restrict__ b3,
    float* __restrict__ out)
{
    __shared__ float s_w1[MM*HH], s_w2[HH*HH], s_w3[HH], s_b1[HH], s_b2[HH], s_b3;
    const int t = threadIdx.x;
    for (int k = t; k < MM*HH; k += 256) s_w1[k] = w1[k];
    for (int k = t; k < HH*HH; k += 256) s_w2[k] = w2[k];
    if (t < HH) { s_w3[t] = w3[t]; s_b1[t] = b1[t]; s_b2[t] = b2[t]; }
    if (t == 0) s_b3 = b3[0];
    __syncthreads();

    int gt = blockIdx.x * 256 + t;
    int w  = gt >> 3;
    int c  = gt & 7;
    if (c >= 7 || w >= g_nwork) return;

    int i   = g_work[w];
    int cnt = g_wcnt[w];

    float h1[HH];
    #pragma unroll
    for (int h = 0; h < HH; h++) h1[h] = s_b1[h];
    for (int m = 0; m < cnt; m++) {
        int j = g_wmem[w*MM + m];
        float xv = g_b7[j*7 + c];
        #pragma unroll
        for (int h = 0; h < HH; h++) h1[h] += xv * s_w1[m*HH + h];
    }
    #pragma unroll
    for (int h = 0; h < HH; h++) h1[h] = fmaxf(h1[h], 0.0f);
    float h2[HH];
    #pragma unroll
    for (int q = 0; q < HH; q++) h2[q] = s_b2[q];
    #pragma unroll
    for (int h = 0; h < HH; h++) {
        float v = h1[h];
        #pragma unroll
        for (int q = 0; q < HH; q++) h2[q] += v * s_w2[h*HH + q];
    }
    float acc = s_b3;
    #pragma unroll
    for (int q = 0; q < HH; q++) acc += fmaxf(h2[q], 0.0f) * s_w3[q];

    if (c >= 3 && c <= 5) acc = fmaxf(acc, 1e-5f);
    out[i*9 + c] = acc;
}

extern "C" void kernel_launch(void* const* d_in, const int* in_sizes, int n_in,
                              void* d_out, int out_size) {
    const float* pb = (const float*)d_in[0];
    const float* ps = (const float*)d_in[1];
    const int*   pl = (const int*)  d_in[2];
    const float* w1 = (const float*)d_in[3];
    const float* b1 = (const float*)d_in[4];
    const float* w2 = (const float*)d_in[5];
    const float* b2 = (const float*)d_in[6];
    const float* w3 = (const float*)d_in[7];
    const float* b3 = (const float*)d_in[8];
    float* out = (float*)d_out;

    cudaFuncSetAttribute(k_sort, cudaFuncAttributeMaxDynamicSharedMemorySize, SMEM_A);
    k_sort<<<1, 1024, SMEM_A>>>(ps);
    k_gather<<<16, 256>>>(pb, ps, pl, out);
    k_build<<<16, 256>>>();
    k_fix<<<1, 1024>>>(out);
    k_merge<<<64, 256>>>(w1, b1, w2, b2, w3, b3, out);
}